// round 6
// baseline (speedup 1.0000x reference)
#include <cuda_runtime.h>
#include <stdint.h>

// Loihi CUBA constants
#define AI 0.75f       // (4096-1024)/4096
#define AV 0.96875f    // (4096-128)/4096
#define TH 100.0f

// Predicated quad-MAC: if (bitv) { a01 += w01 (f32x2); a23 += w23 (f32x2); }
#define QMAC(a01, a23, bitv, w01, w23)                                   \
    asm("{ .reg .pred p;\n\t"                                            \
        "setp.ne.u32 p, %2, 0;\n\t"                                      \
        "@p add.rn.f32x2 %0, %0, %3;\n\t"                                \
        "@p add.rn.f32x2 %1, %1, %4; }"                                  \
        : "+l"(a01), "+l"(a23) : "r"(bitv), "l"(w01), "l"(w23))

__device__ __forceinline__ float2 u64f2(unsigned long long v) {
    float2 f; asm("mov.b64 {%0, %1}, %2;" : "=f"(f.x), "=f"(f.y) : "l"(v)); return f;
}

// ---------------------------------------------------------------------------
// Bitpacked spike buffers: bit k of word j (of 4) = spike at t = j*32 + k.
// Intermediate buffers store the DELAYED stream (<<1 done at producer).
// ---------------------------------------------------------------------------
__device__ uint32_t g_s0[16 * 2  * 40 * 40 * 4];   // packed raw input spikes
__device__ uint32_t g_s1[16 * 8  * 40 * 40 * 4];   // conv1+LIF out (delayed)
__device__ uint32_t g_s2[16 * 8  * 20 * 20 * 4];   // pool1+LIF out (delayed)
__device__ uint32_t g_s3[16 * 16 * 20 * 20 * 4];   // conv2+LIF out (delayed)
__device__ uint32_t g_s4[16 * 16 * 10 * 10 * 4];   // pool2+LIF out (delayed)
__device__ uint32_t g_s5[16 * 3200 * 4];           // conv3+LIF out (delayed, fc layout)
__device__ float    g_wt[3200 * 512];              // fc weights transposed [c][o]
__device__ float    g_x6p[4 * 16 * 512 * 128];     // fc pre-activations (4 c-partials)

// ---------------------------------------------------------------------------
// K0: pack raw float spikes [16,2,40,40,128] (t contiguous) -> bit words
// ---------------------------------------------------------------------------
__global__ void k_pack(const float* __restrict__ sp) {
    int idx = blockIdx.x * blockDim.x + threadIdx.x;   // (n,c,h,w), 51200 total
    const float4* p = (const float4*)(sp + (size_t)idx * 128);
    uint32_t w[4];
#pragma unroll
    for (int j = 0; j < 4; j++) {
        uint32_t b = 0;
#pragma unroll
        for (int q = 0; q < 8; q++) {
            float4 v = p[j * 8 + q];
            b |= (v.x > 0.5f ? 1u : 0u) << (q * 4 + 0);
            b |= (v.y > 0.5f ? 1u : 0u) << (q * 4 + 1);
            b |= (v.z > 0.5f ? 1u : 0u) << (q * 4 + 2);
            b |= (v.w > 0.5f ? 1u : 0u) << (q * 4 + 3);
        }
        w[j] = b;
    }
    *((uint4*)&g_s0[(size_t)idx * 4]) = make_uint4(w[0], w[1], w[2], w[3]);
}

// ---------------------------------------------------------------------------
// K_wt: transpose fc weights [512 o][3200 c] -> g_wt [3200 c][512 o]
// ---------------------------------------------------------------------------
__global__ void k_wt(const float* __restrict__ W) {
    __shared__ float tile[32][33];
    int cb = blockIdx.x * 32, ob = blockIdx.y * 32;
    int x = threadIdx.x, y = threadIdx.y;   // 32, 8
#pragma unroll
    for (int r = 0; r < 32; r += 8)
        tile[y + r][x] = W[(size_t)(ob + y + r) * 3200 + cb + x];
    __syncthreads();
#pragma unroll
    for (int r = 0; r < 32; r += 8)
        g_wt[(size_t)(cb + y + r) * 512 + ob + x] = tile[x][y + r];
}

// ---------------------------------------------------------------------------
// K_convq: dense branch-free 3x3 conv (pad 1) + in-register LIF, delayed out.
// thread = (pixel, o-quad). Per tap-word: 1 LDG + 1 LDS.128 + 16 x QMAC.
// grid = (ceil(H*H/PXB), 16 n), block = PXB * (COUT/4).
// ---------------------------------------------------------------------------
template <int CIN, int H, int COUT, int PXB>
__global__ void __launch_bounds__(128) k_convq(
    const uint32_t* __restrict__ in, uint32_t* __restrict__ out,
    const float* __restrict__ wsrc, float wscale)
{
    constexpr int NQ = COUT / 4;
    constexpr int NTAPS = CIN * 9;
    __shared__ float shw[NTAPS * COUT];     // [tap=(c*9+dy*3+dx)][o]

    int n = blockIdx.y;
    int tid = threadIdx.x;
    constexpr int NTH = PXB * NQ;
    for (int i = tid; i < NTAPS * COUT; i += NTH) {
        int o = i % COUT, tap = i / COUT;
        int c = tap / 9, dydx = tap % 9;
        shw[i] = wsrc[(o * CIN + c) * 9 + dydx] * wscale;
    }
    __syncthreads();

    int q = tid % NQ;
    int px = blockIdx.x * PXB + tid / NQ;
    if (px >= H * H) return;
    int h = px / H, w = px % H;

    const uint32_t* ibase = in + (size_t)n * CIN * H * H * 4;

    float u[4] = {0.f, 0.f, 0.f, 0.f}, v[4] = {0.f, 0.f, 0.f, 0.f};
    uint32_t prevmsb[4] = {0, 0, 0, 0};

    for (int j = 0; j < 4; j++) {
        uint32_t bits[4] = {0, 0, 0, 0};
        for (int half = 0; half < 2; half++) {
            unsigned long long a01[16], a23[16];
#pragma unroll
            for (int k = 0; k < 16; k++) { a01[k] = 0ull; a23[k] = 0ull; }

            for (int c = 0; c < CIN; c++) {
                const uint32_t* cbase = ibase + (size_t)c * H * H * 4;
#pragma unroll
                for (int dy = 0; dy < 3; dy++) {
                    int hh = h + dy - 1;
                    bool hv = (hh >= 0) && (hh < H);
#pragma unroll
                    for (int dx = 0; dx < 3; dx++) {
                        int ww = w + dx - 1;
                        uint32_t word = 0;
                        if (hv && ww >= 0 && ww < H)
                            word = cbase[(hh * H + ww) * 4 + j];
                        uint32_t hw = word >> (half * 16);
                        ulonglong2 wq = *(const ulonglong2*)
                            &shw[(c * 9 + dy * 3 + dx) * COUT + 4 * q];
#pragma unroll
                        for (int k = 0; k < 16; k++)
                            QMAC(a01[k], a23[k], hw & (1u << k), wq.x, wq.y);
                    }
                }
            }
            // LIF over these 16 timesteps (t = half*16 + k), 4 outputs
#pragma unroll
            for (int k = 0; k < 16; k++) {
                float2 f0 = u64f2(a01[k]), f1 = u64f2(a23[k]);
                float x[4] = {f0.x, f0.y, f1.x, f1.y};
                int t = half * 16 + k;
#pragma unroll
                for (int o = 0; o < 4; o++) {
                    u[o] = AI * u[o] + x[o];
                    v[o] = AV * v[o] + u[o];
                    if (v[o] >= TH) { bits[o] |= 1u << t; v[o] = 0.f; }
                }
            }
        }
        // emit delayed words for this j
#pragma unroll
        for (int o = 0; o < 4; o++) {
            uint32_t d = (bits[o] << 1) | prevmsb[o];
            prevmsb[o] = bits[o] >> 31;
            out[(((size_t)(n * COUT + 4 * q + o)) * H * H + px) * 4 + j] = d;
        }
    }
}

// ---------------------------------------------------------------------------
// K2: 2x2 sum pool (* pool_w scalar) + LIF -> out (delayed). Generic.
// ---------------------------------------------------------------------------
__global__ void k_pool(const uint32_t* __restrict__ in, uint32_t* __restrict__ out,
                       int C, int Hin, const float* __restrict__ pw) {
    int Ho = Hin / 2;
    int idx = blockIdx.x * blockDim.x + threadIdx.x;   // (n,c,ph,pw)
    int pwi = idx % Ho;
    int t = idx / Ho;
    int phi = t % Ho; t /= Ho;
    int c = t % C;
    int n = t / C;
    float scale = pw[0];

    const uint32_t* b00 = &in[((((n * C + c) * Hin + 2 * phi) * Hin) + 2 * pwi) * 4];
    const uint32_t* b10 = b00 + Hin * 4;

    float u = 0.f, v = 0.f;
    uint32_t ow[4];
#pragma unroll
    for (int j = 0; j < 4; j++) {
        uint32_t a = b00[j], bb = b00[4 + j], cc = b10[j], d = b10[4 + j];
        uint32_t bits = 0;
#pragma unroll
        for (int k = 0; k < 32; k++) {
            int cnt = (int)((a >> k) & 1u) + (int)((bb >> k) & 1u)
                    + (int)((cc >> k) & 1u) + (int)((d >> k) & 1u);
            float x = (float)cnt * scale;
            u = AI * u + x;
            v = AV * v + u;
            if (v >= TH) { bits |= 1u << k; v = 0.f; }
        }
        ow[j] = bits;
    }
    uint32_t d0 = ow[0] << 1;
    uint32_t d1 = (ow[1] << 1) | (ow[0] >> 31);
    uint32_t d2 = (ow[2] << 1) | (ow[1] >> 31);
    uint32_t d3 = (ow[3] << 1) | (ow[2] >> 31);
    *((uint4*)&out[(size_t)idx * 4]) = make_uint4(d0, d1, d2, d3);
}

// ---------------------------------------------------------------------------
// K_fcd: dense branch-free FC. grid = (4 tt, 16 n, 4 cs), block 256 =
// 128 o-quads x 2 th (16 t each). Per c: LDG.128 W^T quad + uniform word LDS
// + 16 x QMAC. No W smem staging (L1/L2 direct, fully overlapped).
// ---------------------------------------------------------------------------
__global__ void __launch_bounds__(256) k_fcd(float* __restrict__ x6p) {
    __shared__ uint32_t sB[800];

    int tt = blockIdx.x, n = blockIdx.y, cs = blockIdx.z;
    int tid = threadIdx.x;
    int q = tid & 127;       // o-quad: o = 4q..4q+3
    int th = tid >> 7;       // 0..1: t = tt*32 + th*16 + k

    for (int i = tid; i < 800; i += 256)
        sB[i] = g_s5[((size_t)n * 3200 + cs * 800 + i) * 4 + tt];
    __syncthreads();

    unsigned long long a01[16], a23[16];
#pragma unroll
    for (int k = 0; k < 16; k++) { a01[k] = 0ull; a23[k] = 0ull; }

    const float* wp = g_wt + (size_t)(cs * 800) * 512 + 4 * q;
    int hsh = th * 16;

#pragma unroll 2
    for (int c = 0; c < 800; c++) {
        ulonglong2 wq = *(const ulonglong2*)(wp + (size_t)c * 512);
        uint32_t hw = sB[c] >> hsh;
#pragma unroll
        for (int k = 0; k < 16; k++)
            QMAC(a01[k], a23[k], hw & (1u << k), wq.x, wq.y);
    }

    float* base = x6p + ((size_t)(cs * 16 + n) * 512 + 4 * q) * 128 + tt * 32 + th * 16;
#pragma unroll
    for (int k = 0; k < 16; k++) {
        float2 f0 = u64f2(a01[k]), f1 = u64f2(a23[k]);
        base[0 * 128 + k] = f0.x;
        base[1 * 128 + k] = f0.y;
        base[2 * 128 + k] = f1.x;
        base[3 * 128 + k] = f1.y;
    }
}

// ---------------------------------------------------------------------------
// K7: final LIF over sum of 4 partials + output delay-shift -> d_out
// ---------------------------------------------------------------------------
__global__ void k_lif_out(const float* __restrict__ x6p, float* __restrict__ out) {
    const size_t S = (size_t)16 * 512 * 128;
    int idx = blockIdx.x * blockDim.x + threadIdx.x;   // (n,o), 8192 total
    const float* a = &x6p[(size_t)idx * 128];
    float* op = &out[(size_t)idx * 128];
    float u = 0.f, v = 0.f, prev = 0.f;
#pragma unroll 8
    for (int t = 0; t < 128; t++) {
        op[t] = prev;
        float x = (a[t] + a[t + S]) + (a[t + 2 * S] + a[t + 3 * S]);
        u = AI * u + x;
        v = AV * v + u;
        if (v >= TH) { prev = 1.f; v = 0.f; } else { prev = 0.f; }
    }
}

// ---------------------------------------------------------------------------
extern "C" void kernel_launch(void* const* d_in, const int* in_sizes, int n_in,
                              void* d_out, int out_size) {
    const float* spike = (const float*)d_in[0];
    const float* c1w   = (const float*)d_in[1];
    const float* c2w   = (const float*)d_in[2];
    const float* c3w   = (const float*)d_in[3];
    const float* p1w   = (const float*)d_in[4];
    const float* p2w   = (const float*)d_in[5];
    const float* fcw   = (const float*)d_in[6];
    float* out = (float*)d_out;

    uint32_t *s0, *s1, *s2, *s3, *s4, *s5;
    float* x6p;
    cudaGetSymbolAddress((void**)&s0, g_s0);
    cudaGetSymbolAddress((void**)&s1, g_s1);
    cudaGetSymbolAddress((void**)&s2, g_s2);
    cudaGetSymbolAddress((void**)&s3, g_s3);
    cudaGetSymbolAddress((void**)&s4, g_s4);
    cudaGetSymbolAddress((void**)&s5, g_s5);
    cudaGetSymbolAddress((void**)&x6p, g_x6p);

    k_pack<<<200, 256>>>(spike);
    k_wt<<<dim3(100, 16), dim3(32, 8)>>>(fcw);           // W -> g_wt (transposed)
    k_convq<2, 40, 8, 64><<<dim3(25, 16), 128>>>(s0, s1, c1w, 20.0f);
    k_pool<<<200, 256>>>(s1, s2, 8, 40, p1w);            // -> g_s2
    k_convq<8, 20, 16, 32><<<dim3(13, 16), 128>>>(s2, s3, c2w, 100.0f);
    k_pool<<<100, 256>>>(s3, s4, 16, 20, p2w);           // -> g_s4
    k_convq<16, 10, 32, 8><<<dim3(13, 16), 64>>>(s4, s5, c3w, 100.0f);
    k_fcd<<<dim3(4, 16, 4), 256>>>(x6p);                 // -> x6p (4 c-partials)
    k_lif_out<<<32, 256>>>(x6p, out);
}

// round 8
// speedup vs baseline: 2.7030x; 2.7030x over previous
#include <cuda_runtime.h>
#include <cuda_bf16.h>
#include <mma.h>
#include <stdint.h>

using namespace nvcuda;

// Loihi CUBA constants
#define AI 0.75f
#define AV 0.96875f
#define TH 100.0f

__device__ __forceinline__ void add2(unsigned long long& a, unsigned long long b) {
    asm("add.rn.f32x2 %0, %0, %1;" : "+l"(a) : "l"(b));
}
__device__ __forceinline__ float2 u64f2(unsigned long long v) {
    float2 f; asm("mov.b64 {%0, %1}, %2;" : "=f"(f.x), "=f"(f.y) : "l"(v)); return f;
}

// ---------------------------------------------------------------------------
// Buffers (bit k of word j = spike at t = j*32+k; all streams pre-delayed)
// ---------------------------------------------------------------------------
__device__ uint32_t g_s0[16 * 2  * 40 * 40 * 4];
__device__ uint32_t g_s1[16 * 8  * 40 * 40 * 4];
__device__ uint32_t g_s2[16 * 8  * 20 * 20 * 4];
__device__ uint32_t g_s3[16 * 16 * 20 * 20 * 4];
__device__ uint32_t g_s4[16 * 16 * 10 * 10 * 4];
__device__ uint32_t g_s5[16 * 3200 * 4];
__device__ uint32_t g_sb[16 * 128 * 100];           // c-major words per (n,t)
__device__ uint8_t  g_cp1[16 * 22 * 22 * 128];
__device__ uint16_t g_cp2[16 * 12 * 12 * 128];
__device__ __nv_bfloat16 g_wh[3 * 512 * 3200];      // W bf16 splits (hi/mid/lo)
__device__ float    g_dp2[2 * 16 * 512 * 128];      // fc partials (2 c-halves)

// ---------------------------------------------------------------------------
// K0: pack raw float spikes -> bit words
// ---------------------------------------------------------------------------
__global__ void k_pack(const float* __restrict__ sp) {
    int idx = blockIdx.x * blockDim.x + threadIdx.x;
    const float4* p = (const float4*)(sp + (size_t)idx * 128);
    uint32_t w[4];
#pragma unroll
    for (int j = 0; j < 4; j++) {
        uint32_t b = 0;
#pragma unroll
        for (int q = 0; q < 8; q++) {
            float4 v = p[j * 8 + q];
            b |= (v.x > 0.5f ? 1u : 0u) << (q * 4 + 0);
            b |= (v.y > 0.5f ? 1u : 0u) << (q * 4 + 1);
            b |= (v.z > 0.5f ? 1u : 0u) << (q * 4 + 2);
            b |= (v.w > 0.5f ? 1u : 0u) << (q * 4 + 3);
        }
        w[j] = b;
    }
    *((uint4*)&g_s0[(size_t)idx * 4]) = make_uint4(w[0], w[1], w[2], w[3]);
}

// ---------------------------------------------------------------------------
// K_wsplit: W fp32 -> 3 bf16 splits (hi, mid, lo), row-major [s][o][c]
// ---------------------------------------------------------------------------
__global__ void k_wsplit(const float* __restrict__ W) {
    int i = blockIdx.x * blockDim.x + threadIdx.x;   // 819200 pairs
    float a = W[2 * i], b = W[2 * i + 1];
    __nv_bfloat16 ha = __float2bfloat16(a), hb = __float2bfloat16(b);
    float ra = a - __bfloat162float(ha), rb = b - __bfloat162float(hb);
    __nv_bfloat16 ma = __float2bfloat16(ra), mb = __float2bfloat16(rb);
    float sa = ra - __bfloat162float(ma), sb = rb - __bfloat162float(mb);
    __nv_bfloat16 la = __float2bfloat16(sa), lb = __float2bfloat16(sb);
    uint32_t* g = (uint32_t*)g_wh;
    uint16_t uha = *(uint16_t*)&ha, uhb = *(uint16_t*)&hb;
    uint16_t uma = *(uint16_t*)&ma, umb = *(uint16_t*)&mb;
    uint16_t ula = *(uint16_t*)&la, ulb = *(uint16_t*)&lb;
    g[i]               = (uint32_t)uha | ((uint32_t)uhb << 16);
    g[819200 + i]      = (uint32_t)uma | ((uint32_t)umb << 16);
    g[2 * 819200 + i]  = (uint32_t)ula | ((uint32_t)ulb << 16);
}

// ---------------------------------------------------------------------------
// K1: conv1 dense bit path + LIF -> g_s1 (delayed)
// ---------------------------------------------------------------------------
__global__ void k_conv1(const float* __restrict__ cw) {
    __shared__ uint32_t sh[2 * 3 * 42 * 4];
    int b = blockIdx.x;
    int n = b / 40, h = b % 40;
    int tid = threadIdx.x;

    for (int i = tid; i < 2 * 3 * 42 * 4; i += 320) {
        int j = i & 3;
        int t2 = i >> 2;
        int wx = t2 % 42;
        int t3 = t2 / 42;
        int dy = t3 % 3;
        int c  = t3 / 3;
        int r = h - 1 + dy, ws = wx - 1;
        uint32_t v = 0;
        if (r >= 0 && r < 40 && ws >= 0 && ws < 40)
            v = g_s0[(((n * 2 + c) * 40 + r) * 40 + ws) * 4 + j];
        sh[i] = v;
    }
    __syncthreads();

    int w = tid % 40, o = tid / 40;
    float wg[18];
#pragma unroll
    for (int i = 0; i < 18; i++) wg[i] = cw[o * 18 + i] * 20.0f;

    float u = 0.f, v = 0.f;
    uint32_t ow[4];
#pragma unroll
    for (int j = 0; j < 4; j++) {
        float acc[32];
#pragma unroll
        for (int k = 0; k < 32; k++) acc[k] = 0.f;
#pragma unroll
        for (int c = 0; c < 2; c++)
#pragma unroll
        for (int dy = 0; dy < 3; dy++)
#pragma unroll
        for (int dx = 0; dx < 3; dx++) {
            uint32_t wd = sh[(((c * 3 + dy) * 42) + (w + dx)) * 4 + j];
            float wt = wg[c * 9 + dy * 3 + dx];
#pragma unroll
            for (int k = 0; k < 32; k++)
                if (wd & (1u << k)) acc[k] += wt;
        }
        uint32_t bits = 0;
#pragma unroll
        for (int k = 0; k < 32; k++) {
            u = AI * u + acc[k];
            v = AV * v + u;
            if (v >= TH) { bits |= 1u << k; v = 0.f; }
        }
        ow[j] = bits;
    }
    uint32_t d0 = ow[0] << 1;
    uint32_t d1 = (ow[1] << 1) | (ow[0] >> 31);
    uint32_t d2 = (ow[2] << 1) | (ow[1] >> 31);
    uint32_t d3 = (ow[3] << 1) | (ow[2] >> 31);
    *((uint4*)&g_s1[((((n * 8 + o) * 40 + h) * 40 + w)) * 4]) = make_uint4(d0, d1, d2, d3);
}

// ---------------------------------------------------------------------------
// K2: 2x2 sum pool + LIF -> out (delayed)
// ---------------------------------------------------------------------------
__global__ void k_pool(const uint32_t* __restrict__ in, uint32_t* __restrict__ out,
                       int C, int Hin, const float* __restrict__ pw) {
    int Ho = Hin / 2;
    int idx = blockIdx.x * blockDim.x + threadIdx.x;
    int pwi = idx % Ho;
    int t = idx / Ho;
    int phi = t % Ho; t /= Ho;
    int c = t % C;
    int n = t / C;
    float scale = pw[0];

    const uint32_t* b00 = &in[((((n * C + c) * Hin + 2 * phi) * Hin) + 2 * pwi) * 4];
    const uint32_t* b10 = b00 + Hin * 4;

    float u = 0.f, v = 0.f;
    uint32_t ow[4];
#pragma unroll
    for (int j = 0; j < 4; j++) {
        uint32_t a = b00[j], bb = b00[4 + j], cc = b10[j], d = b10[4 + j];
        uint32_t bits = 0;
#pragma unroll
        for (int k = 0; k < 32; k++) {
            int cnt = (int)((a >> k) & 1u) + (int)((bb >> k) & 1u)
                    + (int)((cc >> k) & 1u) + (int)((d >> k) & 1u);
            float x = (float)cnt * scale;
            u = AI * u + x;
            v = AV * v + u;
            if (v >= TH) { bits |= 1u << k; v = 0.f; }
        }
        ow[j] = bits;
    }
    uint32_t d0 = ow[0] << 1;
    uint32_t d1 = (ow[1] << 1) | (ow[0] >> 31);
    uint32_t d2 = (ow[2] << 1) | (ow[1] >> 31);
    uint32_t d3 = (ow[3] << 1) | (ow[2] >> 31);
    *((uint4*)&out[(size_t)idx * 4]) = make_uint4(d0, d1, d2, d3);
}

// ---------------------------------------------------------------------------
// K2b/K4b: c-major transposes (for sparse convs)
// ---------------------------------------------------------------------------
__global__ void k_tr8() {
    int i = blockIdx.x * blockDim.x + threadIdx.x;
    int n = i / 1600;
    int r = i % 1600;
    int px = r >> 2, j = r & 3;
    uint32_t wc[8];
#pragma unroll
    for (int c = 0; c < 8; c++)
        wc[c] = g_s2[((size_t)((n * 8 + c) * 400 + px)) * 4 + j];
    int h = px / 20, w = px % 20;
    uint8_t* dst = g_cp1 + ((size_t)n * 484 + (h + 1) * 22 + (w + 1)) * 128 + j * 32;
#pragma unroll
    for (int k = 0; k < 32; k += 4) {
        uint32_t v = 0;
#pragma unroll
        for (int q = 0; q < 4; q++) {
            uint32_t byte = 0;
#pragma unroll
            for (int c = 0; c < 8; c++)
                byte |= ((wc[c] >> (k + q)) & 1u) << c;
            v |= byte << (q * 8);
        }
        *(uint32_t*)(dst + k) = v;
    }
}

__global__ void k_tr16() {
    int i = blockIdx.x * blockDim.x + threadIdx.x;
    int n = i / 400;
    int r = i % 400;
    int px = r >> 2, j = r & 3;
    uint32_t wc[16];
#pragma unroll
    for (int c = 0; c < 16; c++)
        wc[c] = g_s4[((size_t)((n * 16 + c) * 100 + px)) * 4 + j];
    int h = px / 10, w = px % 10;
    uint16_t* dst = g_cp2 + ((size_t)n * 144 + (h + 1) * 12 + (w + 1)) * 128 + j * 32;
#pragma unroll
    for (int k = 0; k < 32; k += 2) {
        uint32_t v = 0;
#pragma unroll
        for (int c = 0; c < 16; c++) {
            v |= ((wc[c] >> k) & 1u) << c;
            v |= ((wc[c] >> (k + 1)) & 1u) << (16 + c);
        }
        *(uint32_t*)(dst + k) = v;
    }
}

// ---------------------------------------------------------------------------
// K3: sparse conv2 o-quad (R5, proven)
// ---------------------------------------------------------------------------
__global__ void __launch_bounds__(128) k_conv2s(const float* __restrict__ wsrc) {
    __shared__ float4   shW4[72 * 4];
    __shared__ uint32_t shTW[128 * 3];
    __shared__ float    pre[16 * 129];
    int px = blockIdx.x, n = blockIdx.y;
    int h = px / 20, w = px % 20;
    int tid = threadIdx.x;

    for (int i = tid; i < 72 * 4; i += 128) {
        int q = i & 3, tap = i >> 2;
        int c = tap & 7, dydx = tap >> 3;
        float4 v;
        v.x = wsrc[((4 * q + 0) * 8 + c) * 9 + dydx] * 100.0f;
        v.y = wsrc[((4 * q + 1) * 8 + c) * 9 + dydx] * 100.0f;
        v.z = wsrc[((4 * q + 2) * 8 + c) * 9 + dydx] * 100.0f;
        v.w = wsrc[((4 * q + 3) * 8 + c) * 9 + dydx] * 100.0f;
        shW4[i] = v;
    }
    {
        const uint8_t* base = g_cp1 + ((size_t)n * 484 + h * 22 + w) * 128 + tid;
        uint32_t b[9];
#pragma unroll
        for (int dy = 0; dy < 3; dy++)
#pragma unroll
            for (int dx = 0; dx < 3; dx++)
                b[dy * 3 + dx] = base[(dy * 22 + dx) * 128];
        shTW[tid * 3 + 0] = b[0] | (b[1] << 8) | (b[2] << 16) | (b[3] << 24);
        shTW[tid * 3 + 1] = b[4] | (b[5] << 8) | (b[6] << 16) | (b[7] << 24);
        shTW[tid * 3 + 2] = b[8];
    }
    __syncthreads();

    int q = tid & 3, tq = tid >> 2;
#pragma unroll
    for (int i = 0; i < 4; i++) {
        int t = tq * 4 + i;
        uint32_t s0 = shTW[t * 3], s1 = shTW[t * 3 + 1], s2 = shTW[t * 3 + 2];
        unsigned long long a0 = 0ull, a1 = 0ull;
        while (s0) {
            int k = __ffs(s0) - 1; s0 &= s0 - 1;
            const ulonglong2 wv = *(const ulonglong2*)&shW4[k * 4 + q];
            add2(a0, wv.x); add2(a1, wv.y);
        }
        while (s1) {
            int k = __ffs(s1) - 1; s1 &= s1 - 1;
            const ulonglong2 wv = *(const ulonglong2*)&shW4[(32 + k) * 4 + q];
            add2(a0, wv.x); add2(a1, wv.y);
        }
        while (s2) {
            int k = __ffs(s2) - 1; s2 &= s2 - 1;
            const ulonglong2 wv = *(const ulonglong2*)&shW4[(64 + k) * 4 + q];
            add2(a0, wv.x); add2(a1, wv.y);
        }
        float2 f0 = u64f2(a0), f1 = u64f2(a1);
        pre[(4 * q + 0) * 129 + t] = f0.x;
        pre[(4 * q + 1) * 129 + t] = f0.y;
        pre[(4 * q + 2) * 129 + t] = f1.x;
        pre[(4 * q + 3) * 129 + t] = f1.y;
    }
    __syncthreads();

    if (tid < 16) {
        float u = 0.f, v = 0.f;
        uint32_t ow[4];
#pragma unroll
        for (int j = 0; j < 4; j++) {
            uint32_t bits = 0;
#pragma unroll
            for (int k = 0; k < 32; k++) {
                u = AI * u + pre[tid * 129 + j * 32 + k];
                v = AV * v + u;
                if (v >= TH) { bits |= 1u << k; v = 0.f; }
            }
            ow[j] = bits;
        }
        uint32_t d0 = ow[0] << 1;
        uint32_t d1 = (ow[1] << 1) | (ow[0] >> 31);
        uint32_t d2 = (ow[2] << 1) | (ow[1] >> 31);
        uint32_t d3 = (ow[3] << 1) | (ow[2] >> 31);
        *((uint4*)&g_s3[((size_t)((n * 16 + tid) * 400 + px)) * 4]) =
            make_uint4(d0, d1, d2, d3);
    }
}

// ---------------------------------------------------------------------------
// K5: sparse conv3 o-quad (R5, proven)
// ---------------------------------------------------------------------------
__global__ void __launch_bounds__(128) k_conv3s(const float* __restrict__ wsrc) {
    __shared__ float4   shW4[144 * 8];
    __shared__ uint32_t shTW[128 * 5];
    __shared__ float    pre[32 * 129];
    int px = blockIdx.x, n = blockIdx.y;
    int h = px / 10, w = px % 10;
    int tid = threadIdx.x;

    for (int i = tid; i < 144 * 8; i += 128) {
        int q = i & 7, tap = i >> 3;
        int c = tap & 15, dydx = tap >> 4;
        float4 v;
        v.x = wsrc[((4 * q + 0) * 16 + c) * 9 + dydx] * 100.0f;
        v.y = wsrc[((4 * q + 1) * 16 + c) * 9 + dydx] * 100.0f;
        v.z = wsrc[((4 * q + 2) * 16 + c) * 9 + dydx] * 100.0f;
        v.w = wsrc[((4 * q + 3) * 16 + c) * 9 + dydx] * 100.0f;
        shW4[i] = v;
    }
    {
        const uint16_t* base = g_cp2 + ((size_t)n * 144 + h * 12 + w) * 128 + tid;
        uint32_t b[9];
#pragma unroll
        for (int dy = 0; dy < 3; dy++)
#pragma unroll
            for (int dx = 0; dx < 3; dx++)
                b[dy * 3 + dx] = base[(dy * 12 + dx) * 128];
        shTW[tid * 5 + 0] = b[0] | (b[1] << 16);
        shTW[tid * 5 + 1] = b[2] | (b[3] << 16);
        shTW[tid * 5 + 2] = b[4] | (b[5] << 16);
        shTW[tid * 5 + 3] = b[6] | (b[7] << 16);
        shTW[tid * 5 + 4] = b[8];
    }
    __syncthreads();

    int q = tid & 7, tq = tid >> 3;
#pragma unroll
    for (int i = 0; i < 8; i++) {
        int t = tq * 8 + i;
        unsigned long long a0 = 0ull, a1 = 0ull;
#pragma unroll
        for (int m = 0; m < 5; m++) {
            uint32_t s = shTW[t * 5 + m];
            while (s) {
                int k = __ffs(s) - 1; s &= s - 1;
                const ulonglong2 wv = *(const ulonglong2*)&shW4[(m * 32 + k) * 8 + q];
                add2(a0, wv.x); add2(a1, wv.y);
            }
        }
        float2 f0 = u64f2(a0), f1 = u64f2(a1);
        pre[(4 * q + 0) * 129 + t] = f0.x;
        pre[(4 * q + 1) * 129 + t] = f0.y;
        pre[(4 * q + 2) * 129 + t] = f1.x;
        pre[(4 * q + 3) * 129 + t] = f1.y;
    }
    __syncthreads();

    if (tid < 32) {
        float u = 0.f, v = 0.f;
        uint32_t ow[4];
#pragma unroll
        for (int j = 0; j < 4; j++) {
            uint32_t bits = 0;
#pragma unroll
            for (int k = 0; k < 32; k++) {
                u = AI * u + pre[tid * 129 + j * 32 + k];
                v = AV * v + u;
                if (v >= TH) { bits |= 1u << k; v = 0.f; }
            }
            ow[j] = bits;
        }
        uint32_t d0 = ow[0] << 1;
        uint32_t d1 = (ow[1] << 1) | (ow[0] >> 31);
        uint32_t d2 = (ow[2] << 1) | (ow[1] >> 31);
        uint32_t d3 = (ow[3] << 1) | (ow[2] >> 31);
        *((uint4*)&g_s5[((size_t)(n * 3200 + tid * 100 + px)) * 4]) =
            make_uint4(d0, d1, d2, d3);
    }
}

// ---------------------------------------------------------------------------
// K5b: bit transpose t-major -> c-major (ballot)
// ---------------------------------------------------------------------------
__global__ void k_trans() {
    int gw = (blockIdx.x * blockDim.x + threadIdx.x) >> 5;
    int lane = threadIdx.x & 31;
    int n = gw / 400;
    int r = gw % 400;
    int cw = r >> 2;
    int j = r & 3;
    uint32_t w = g_s5[((size_t)n * 3200 + cw * 32 + lane) * 4 + j];
    uint32_t out = 0;
#pragma unroll
    for (int b = 0; b < 32; b++) {
        uint32_t bl = __ballot_sync(0xffffffffu, (w >> b) & 1u);
        if (lane == b) out = bl;
    }
    g_sb[((size_t)n * 128 + j * 32 + lane) * 100 + cw] = out;
}

// ---------------------------------------------------------------------------
// K_fcw: WMMA bf16 FC. grid (4 ot, 16 n, 2 cs), block 256 = 8 warps.
// D[128 o][128 t] += sum over chunks x 3 W-splits of A[128,128]·B[128,128]^T.
// A = W split chunk (row-major), B = spikes [t][c] (col-major for wmma).
// cs0: chunks 0..12, cs1: 13..24.
// ---------------------------------------------------------------------------
__global__ void __launch_bounds__(256) k_fcw(float* __restrict__ dp) {
    extern __shared__ __align__(16) __nv_bfloat16 sm[];
    __nv_bfloat16* sA = sm;              // [128][136]
    __nv_bfloat16* sB = sm + 128 * 136;  // [128][136]

    int ot = blockIdx.x, n = blockIdx.y, cs = blockIdx.z;
    int tid = threadIdx.x;
    int warp = tid >> 5;
    int wy = warp >> 2, wx = warp & 3;   // warp tile: o [wy*64,+64) x t [wx*32,+32)

    int cbeg = cs ? 13 : 0;
    int cend = cs ? 25 : 13;

    wmma::fragment<wmma::accumulator, 16, 16, 16, float> acc[4][2];
#pragma unroll
    for (int i = 0; i < 4; i++)
#pragma unroll
        for (int j = 0; j < 2; j++)
            wmma::fill_fragment(acc[i][j], 0.0f);

    for (int cc = cbeg; cc < cend; cc++) {
        __syncthreads();
        // stage B [128 t][128 c] from bit words
        {
            int t = tid >> 1, half = tid & 1;
            const uint32_t* src = g_sb + ((size_t)n * 128 + t) * 100 + cc * 4 + half * 2;
            uint32_t w0 = src[0], w1 = src[1];
            uint32_t* d32 = (uint32_t*)(sB + t * 136 + half * 64);
#pragma unroll
            for (int b = 0; b < 16; b++)
                d32[b] = (((w0 >> (2 * b)) & 1u) ? 0x3F80u : 0u)
                       | (((w0 >> (2 * b + 1)) & 1u) ? 0x3F800000u : 0u);
#pragma unroll
            for (int b = 0; b < 16; b++)
                d32[16 + b] = (((w1 >> (2 * b)) & 1u) ? 0x3F80u : 0u)
                            | (((w1 >> (2 * b + 1)) & 1u) ? 0x3F800000u : 0u);
        }

        for (int s = 0; s < 3; s++) {
            if (s > 0) __syncthreads();   // all warps done reading previous sA
            // stage A split s: [128 o][128 c]
            {
                const uint4* src = (const uint4*)
                    (g_wh + ((size_t)s * 512 + ot * 128) * 3200 + cc * 128);
#pragma unroll
                for (int r8 = 0; r8 < 8; r8++) {
                    int i = tid + r8 * 256;       // 0..2047
                    int r = i >> 4, q2 = i & 15;
                    uint4 v = src[(size_t)r * 400 + q2];
                    *(uint4*)&sA[r * 136 + q2 * 8] = v;
                }
            }
            __syncthreads();

#pragma unroll
            for (int k8 = 0; k8 < 8; k8++) {
                wmma::fragment<wmma::matrix_a, 16, 16, 16, __nv_bfloat16,
                               wmma::row_major> af[4];
                wmma::fragment<wmma::matrix_b, 16, 16, 16, __nv_bfloat16,
                               wmma::col_major> bf[2];
#pragma unroll
                for (int i = 0; i < 4; i++)
                    wmma::load_matrix_sync(af[i],
                        sA + (wy * 64 + i * 16) * 136 + k8 * 16, 136);
#pragma unroll
                for (int j = 0; j < 2; j++)
                    wmma::load_matrix_sync(bf[j],
                        sB + (wx * 32 + j * 16) * 136 + k8 * 16, 136);
#pragma unroll
                for (int i = 0; i < 4; i++)
#pragma unroll
                    for (int j = 0; j < 2; j++)
                        wmma::mma_sync(acc[i][j], af[i], bf[j], acc[i][j]);
            }
        }
    }

    // store partial D
    float* base = dp + ((size_t)(cs * 16 + n) * 512 + ot * 128) * 128;
#pragma unroll
    for (int i = 0; i < 4; i++)
#pragma unroll
        for (int j = 0; j < 2; j++)
            wmma::store_matrix_sync(
                base + (wy * 64 + i * 16) * 128 + wx * 32 + j * 16,
                acc[i][j], 128, wmma::mem_row_major);
}

// ---------------------------------------------------------------------------
// K_lif2: sum 2 partials + LIF + output delay-shift -> d_out
// ---------------------------------------------------------------------------
__global__ void k_lif2(float* __restrict__ out) {
    const size_t S = (size_t)16 * 512 * 128;
    int idx = blockIdx.x * blockDim.x + threadIdx.x;
    const float* a = &g_dp2[(size_t)idx * 128];
    float* op = &out[(size_t)idx * 128];
    float u = 0.f, v = 0.f, prev = 0.f;
#pragma unroll 8
    for (int t = 0; t < 128; t++) {
        op[t] = prev;
        float x = a[t] + a[t + S];
        u = AI * u + x;
        v = AV * v + u;
        if (v >= TH) { prev = 1.f; v = 0.f; } else { prev = 0.f; }
    }
}

// ---------------------------------------------------------------------------
extern "C" void kernel_launch(void* const* d_in, const int* in_sizes, int n_in,
                              void* d_out, int out_size) {
    const float* spike = (const float*)d_in[0];
    const float* c1w   = (const float*)d_in[1];
    const float* c2w   = (const float*)d_in[2];
    const float* c3w   = (const float*)d_in[3];
    const float* p1w   = (const float*)d_in[4];
    const float* p2w   = (const float*)d_in[5];
    const float* fcw   = (const float*)d_in[6];
    float* out = (float*)d_out;

    uint32_t *s1, *s2, *s3, *s4;
    float* dp;
    cudaGetSymbolAddress((void**)&s1, g_s1);
    cudaGetSymbolAddress((void**)&s2, g_s2);
    cudaGetSymbolAddress((void**)&s3, g_s3);
    cudaGetSymbolAddress((void**)&s4, g_s4);
    cudaGetSymbolAddress((void**)&dp, g_dp2);

    const int FCW_SMEM = 2 * 128 * 136 * 2;   // 69632 B
    cudaFuncSetAttribute((const void*)k_fcw,
                         cudaFuncAttributeMaxDynamicSharedMemorySize, FCW_SMEM);

    k_pack<<<200, 256>>>(spike);
    k_wsplit<<<3200, 256>>>(fcw);                      // W -> 3 bf16 splits
    k_conv1<<<640, 320>>>(c1w);
    k_pool<<<200, 256>>>(s1, s2, 8, 40, p1w);
    k_tr8<<<100, 256>>>();
    k_conv2s<<<dim3(400, 16), 128>>>(c2w);
    k_pool<<<100, 256>>>(s3, s4, 16, 20, p2w);
    k_tr16<<<25, 256>>>();
    k_conv3s<<<dim3(100, 16), 128>>>(c3w);
    k_trans<<<800, 256>>>();
    k_fcw<<<dim3(4, 16, 2), 256, FCW_SMEM>>>(dp);      // WMMA bf16 FC
    k_lif2<<<32, 256>>>(out);
}